// round 14
// baseline (speedup 1.0000x reference)
#include <cuda_runtime.h>
#include <cuda_fp16.h>
#include <stdint.h>
#include <math.h>

#define T_TOK 8192
#define TT    16384          // 2*T gathered rows
#define D_DIM 1024
#define H_DIM 684
#define HP    704            // H padded to multiple of 64
#define NE    8
#define KW1   1024           // xg1 / w1c / w3c width (single-rounded)
#define KW2   704            // h2_ / w2c width (single-rounded)
#define NCH1  32             // K chunks (1024/32)
#define NCH2  22             // K chunks (704/32)

// ======================= scratch =======================
__device__ __half xg1[(size_t)TT * KW1];
__device__ __half w1c[(size_t)NE * H_DIM * KW1];
__device__ __half w3c[(size_t)NE * H_DIM * KW1];
__device__ __half w2c[(size_t)NE * D_DIM * KW2];
__device__ __half h2_[(size_t)TT * KW2];
__device__ float g_y[(size_t)TT * D_DIM];

__device__ int   g_pos[TT];
__device__ int   g_cnt[NE];
__device__ int   g_cur[NE];
__device__ int   g_top[TT];
__device__ float g_topp[TT];
__device__ int   g_dcnt[NE];
__device__ float g_psum[NE];

// ======================= asm helpers (portable sm_80+) =======================
__device__ __forceinline__ uint32_t smem_to_u32(const void* p) {
    uint32_t a;
    asm("{ .reg .u64 t; cvta.to.shared.u64 t, %1; cvt.u32.u64 %0, t; }" : "=r"(a) : "l"(p));
    return a;
}

__device__ __forceinline__ void cp16(uint32_t dst, const void* src) {
    asm volatile("cp.async.cg.shared.global [%0], [%1], 16;" :: "r"(dst), "l"(src) : "memory");
}
#define CP_COMMIT() asm volatile("cp.async.commit_group;" ::: "memory")
#define CP_WAIT2()  asm volatile("cp.async.wait_group 2;" ::: "memory")

__device__ __forceinline__ void ldsm4(uint32_t* r, uint32_t addr) {
    asm volatile("ldmatrix.sync.aligned.m8n8.x4.shared.b16 {%0,%1,%2,%3}, [%4];"
                 : "=r"(r[0]), "=r"(r[1]), "=r"(r[2]), "=r"(r[3]) : "r"(addr));
}

__device__ __forceinline__ void mma16816(float* c, const uint32_t* a, uint32_t b0, uint32_t b1) {
    asm volatile("mma.sync.aligned.m16n8k16.row.col.f32.f16.f16.f32 "
                 "{%0,%1,%2,%3}, {%4,%5,%6,%7}, {%8,%9}, {%0,%1,%2,%3};"
                 : "+f"(c[0]), "+f"(c[1]), "+f"(c[2]), "+f"(c[3])
                 : "r"(a[0]), "r"(a[1]), "r"(a[2]), "r"(a[3]), "r"(b0), "r"(b1));
}

// ---- fp16 helpers ----
__device__ __forceinline__ void store4_h(__half* base, size_t o, float4 v) {
    *reinterpret_cast<__half2*>(base + o)     = __floats2half2_rn(v.x, v.y);
    *reinterpret_cast<__half2*>(base + o + 2) = __floats2half2_rn(v.z, v.w);
}

// ======================= launch 1: weight conversion + counter init =======================
#define CONV13_BLOCKS 5472   // NE*H*D/4/256
#define CONV2_BLOCKS  5632   // NE*D*176/256
__global__ void k_conv(const float* __restrict__ w1, const float* __restrict__ w3,
                       const float* __restrict__ w2) {
    int bx = blockIdx.x;
    if (bx == 0 && threadIdx.x < NE) {
        g_cnt[threadIdx.x] = 0; g_cur[threadIdx.x] = 0;
        g_dcnt[threadIdx.x] = 0; g_psum[threadIdx.x] = 0.f;
    }
    if (bx < CONV13_BLOCKS) {
        size_t i = (size_t)bx * 256 + threadIdx.x;
        size_t row = i >> 8;
        size_t col = (i & 255) * 4;
        float4 a = reinterpret_cast<const float4*>(w1)[i];
        float4 b = reinterpret_cast<const float4*>(w3)[i];
        store4_h(w1c, row * KW1 + col, a);
        store4_h(w3c, row * KW1 + col, b);
    } else {
        size_t i = (size_t)(bx - CONV13_BLOCKS) * 256 + threadIdx.x;
        size_t row = i / 176;
        int col = (int)(i % 176) * 4;
        float4 v = make_float4(0.f, 0.f, 0.f, 0.f);
        if (col < H_DIM) {
            const float* p = w2 + row * H_DIM + col;
            v.x = p[0];
            v.y = (col + 1 < H_DIM) ? p[1] : 0.f;
            v.z = (col + 2 < H_DIM) ? p[2] : 0.f;
            v.w = (col + 3 < H_DIM) ? p[3] : 0.f;
        }
        store4_h(w2c, row * KW2 + (size_t)col, v);
    }
}

// ======================= launch 2: router =======================
__global__ void k_router(const float* __restrict__ x, const float* __restrict__ rw) {
    __shared__ float s_ps[NE];
    __shared__ int   s_dc[NE];
    __shared__ int   s_cnt[NE];
    int tid = threadIdx.x;
    if (tid < NE) { s_ps[tid] = 0.f; s_dc[tid] = 0; s_cnt[tid] = 0; }
    __syncthreads();

    int warp = tid >> 5, lane = tid & 31;
    int t = blockIdx.x * 8 + warp;

    float xv[32];
    const float* xr = x + (size_t)t * D_DIM;
#pragma unroll
    for (int i = 0; i < 32; i++) xv[i] = xr[lane + 32 * i];

    float logit[NE];
#pragma unroll
    for (int e = 0; e < NE; e++) {
        const float* wr = rw + e * D_DIM;
        float s = 0.f;
#pragma unroll
        for (int i = 0; i < 32; i++) s += xv[i] * wr[lane + 32 * i];
#pragma unroll
        for (int o = 16; o; o >>= 1) s += __shfl_xor_sync(0xffffffffu, s, o);
        logit[e] = s;
    }

    if (lane == 0) {
        float mx = logit[0];
#pragma unroll
        for (int e = 1; e < NE; e++) mx = fmaxf(mx, logit[e]);
        float p[NE], sum = 0.f;
#pragma unroll
        for (int e = 0; e < NE; e++) { p[e] = expf(logit[e] - mx); sum += p[e]; }
        float inv = 1.f / sum;
#pragma unroll
        for (int e = 0; e < NE; e++) p[e] *= inv;

        int i0 = 0;
#pragma unroll
        for (int e = 1; e < NE; e++) if (p[e] > p[i0]) i0 = e;
        int i1 = (i0 == 0) ? 1 : 0;
#pragma unroll
        for (int e = 0; e < NE; e++) if (e != i0 && p[e] > p[i1]) i1 = e;

        g_top[t * 2]      = i0;    g_top[t * 2 + 1]  = i1;
        g_topp[t * 2]     = p[i0]; g_topp[t * 2 + 1] = p[i1];

        atomicAdd(&s_dc[i0], 1);
        atomicAdd(&s_cnt[i0], 1);
        atomicAdd(&s_cnt[i1], 1);
#pragma unroll
        for (int e = 0; e < NE; e++) atomicAdd(&s_ps[e], p[e]);
    }
    __syncthreads();
    if (tid < NE) {
        atomicAdd(&g_psum[tid], s_ps[tid]);
        atomicAdd(&g_dcnt[tid], s_dc[tid]);
        atomicAdd(&g_cnt[tid], s_cnt[tid]);
    }
}

// ======================= launch 3: scatter + gather (single fp16) + aux =======================
__global__ void k_scatgather(const float* __restrict__ x, float* __restrict__ out, int out_size) {
    int wid = threadIdx.x >> 5, lane = threadIdx.x & 31;
    int i = blockIdx.x * 8 + wid;            // slot id

    if (blockIdx.x == 0 && threadIdx.x == 0) {
        float s = 0.f;
        for (int e = 0; e < NE; e++)
            s += ((float)g_dcnt[e] / (float)T_TOK) * (g_psum[e] / (float)T_TOK);
        if (out_size > T_TOK * D_DIM) out[T_TOK * D_DIM] = 0.01f * s * (float)NE;
    }

    int e = g_top[i];
    int pos = 0;
    if (lane == 0) {
        int o = 0;
        for (int k = 0; k < NE; k++) { if (k == e) break; o += g_cnt[k]; }
        pos = o + atomicAdd(&g_cur[e], 1);
        g_pos[i] = pos;
    }
    pos = __shfl_sync(0xffffffffu, pos, 0);

    int tok = i >> 1;
    const float4* xr = reinterpret_cast<const float4*>(x) + (size_t)tok * 256;
#pragma unroll
    for (int j = 0; j < 8; j++) {
        int c = lane + j * 32;
        store4_h(xg1, (size_t)pos * KW1 + (size_t)c * 4, xr[c]);
    }
}

__device__ __forceinline__ int expert_base(int e) {
    int o = 0;
    for (int k = 0; k < e; k++) o += g_cnt[k];
    return o;
}

// ======================= GEMM cores =======================
// 2 CTAs/SM, 256 thr (8 warps).
#define RSTRIDE  80
#define T64_B    5120            // 64 rows * 80B
#define T128_B   10240           // 128 rows * 80B
#define STAGE1   (T128_B + 2*T64_B)   // A(128m) B1(64n) B3(64n) = 20480
#define STAGE2   (2*T128_B)           // A(128m) B(128n)        = 20480

__device__ __forceinline__ void load_a(uint32_t sA, uint32_t a[2][2][4], int warp_m0, int lane) {
#pragma unroll
    for (int mi = 0; mi < 2; mi++)
#pragma unroll
        for (int kh = 0; kh < 2; kh++) {
            uint32_t ad = sA + (warp_m0 + mi*16 + (lane & 15)) * RSTRIDE
                             + (kh*16 + (lane >> 4) * 8) * 2;
            ldsm4(a[mi][kh], ad);
        }
}

// B read inline from smem (transient regs), 16 MMA  (32x32 warp tile)
__device__ __forceinline__ void compute_warp(
    uint32_t sB, const uint32_t a[2][2][4],
    float acc[2][4][4], int warp_n0, int lane)
{
#pragma unroll
    for (int nj2 = 0; nj2 < 2; nj2++) {
#pragma unroll
        for (int kh = 0; kh < 2; kh++) {
            uint32_t r[4];
            uint32_t bd = sB + (warp_n0 + nj2*16 + (lane & 15)) * RSTRIDE
                             + (kh*16 + (lane >> 4) * 8) * 2;
            ldsm4(r, bd);
            mma16816(acc[0][nj2*2 + 0], a[0][kh], r[0], r[2]);
            mma16816(acc[0][nj2*2 + 1], a[0][kh], r[1], r[3]);
            mma16816(acc[1][nj2*2 + 0], a[1][kh], r[0], r[2]);
            mma16816(acc[1][nj2*2 + 1], a[1][kh], r[1], r[3]);
        }
    }
}

// 64x32 warp tile variants (gemm2)
__device__ __forceinline__ void load_a4(uint32_t sA, uint32_t a[4][2][4], int warp_m0, int lane) {
#pragma unroll
    for (int mi = 0; mi < 4; mi++)
#pragma unroll
        for (int kh = 0; kh < 2; kh++) {
            uint32_t ad = sA + (warp_m0 + mi*16 + (lane & 15)) * RSTRIDE
                             + (kh*16 + (lane >> 4) * 8) * 2;
            ldsm4(a[mi][kh], ad);
        }
}

__device__ __forceinline__ void compute_warp4(
    uint32_t sB, const uint32_t a[4][2][4],
    float acc[4][4][4], int warp_n0, int lane)
{
#pragma unroll
    for (int nj2 = 0; nj2 < 2; nj2++) {
#pragma unroll
        for (int kh = 0; kh < 2; kh++) {
            uint32_t r[4];
            uint32_t bd = sB + (warp_n0 + nj2*16 + (lane & 15)) * RSTRIDE
                             + (kh*16 + (lane >> 4) * 8) * 2;
            ldsm4(r, bd);
#pragma unroll
            for (int mi = 0; mi < 4; mi++) {
                mma16816(acc[mi][nj2*2 + 0], a[mi][kh], r[0], r[2]);
                mma16816(acc[mi][nj2*2 + 1], a[mi][kh], r[1], r[3]);
            }
        }
    }
}

// ------- launch 4 (PROFILED): GEMM1, CTA 128m x 64n, 4m x 2n warps, 4-stage -------
__global__ __launch_bounds__(256, 2) void k_gemm1() {
    extern __shared__ char smem[];
    const int e = blockIdx.z;
    const int cnt = g_cnt[e];
    const int m0 = blockIdx.x * 128;
    if (m0 >= cnt) return;
    const int base = expert_base(e);
    const int n0g = blockIdx.y * 64;               // 11 tiles cover 704
    const int tid = threadIdx.x, wid = tid >> 5, lane = tid & 31;
    const int warp_m0 = (wid >> 1) * 32, warp_n0 = (wid & 1) * 32;

    uint32_t sb = smem_to_u32(smem);
    const __half* B1 = w1c + (size_t)e * H_DIM * KW1;
    const __half* B3 = w3c + (size_t)e * H_DIM * KW1;
    const long arow = base + m0;

    // A loader: 128 rows x 4x16B; 256 thr -> 2 cp16 each
    const int arow_t = tid >> 1, ach = (tid & 1) * 2;
    long ar = arow + arow_t; if (ar >= TT) ar = TT - 1;
    const __half* gA = xg1 + ar * (long)KW1 + ach * 8;
    const uint32_t sdA = sb + arow_t * RSTRIDE + ach * 16;

    // B loaders: 64 rows x 4x16B; 256 thr -> 1 cp16 each per tile
    const int brow = tid >> 2, bch = tid & 3;
    int nr = n0g + brow; if (nr > H_DIM - 1) nr = H_DIM - 1;
    const __half* gB1 = B1 + (long)nr * KW1 + bch * 8;
    const __half* gB3 = B3 + (long)nr * KW1 + bch * 8;
    const uint32_t sdB1 = sb + T128_B + brow * RSTRIDE + bch * 16;
    const uint32_t sdB3 = sdB1 + T64_B;

    auto load_stage = [&](int st, int kc) {
        uint32_t d = st * STAGE1;
        int ko = kc * 32;
        cp16(sdA  + d,      gA  + ko);
        cp16(sdA  + d + 16, gA  + ko + 8);
        cp16(sdB1 + d,      gB1 + ko);
        cp16(sdB3 + d,      gB3 + ko);
    };

    float acc1[2][4][4] = {{{0}}}, acc3[2][4][4] = {{{0}}};

    load_stage(0, 0); CP_COMMIT();
    load_stage(1, 1); CP_COMMIT();
    load_stage(2, 2); CP_COMMIT();

    for (int kc = 0; kc < NCH1; kc++) {
        CP_WAIT2();
        __syncthreads();
        if (kc + 3 < NCH1) load_stage((kc + 3) & 3, kc + 3);
        CP_COMMIT();
        uint32_t st = sb + (kc & 3) * STAGE1;
        uint32_t a[2][2][4];
        load_a(st, a, warp_m0, lane);
        compute_warp(st + T128_B,         a, acc1, warp_n0, lane); // A*B1
        compute_warp(st + T128_B + T64_B, a, acc3, warp_n0, lane); // A*B3
    }

    // epilogue: swiglu -> single fp16 h
#pragma unroll
    for (int mi = 0; mi < 2; mi++) {
#pragma unroll
        for (int nj = 0; nj < 4; nj++) {
            int n = n0g + warp_n0 + nj * 8 + ((lane & 3) << 1);
            if (n >= HP) continue;
            bool live = (n < H_DIM);
#pragma unroll
            for (int h = 0; h < 2; h++) {
                int rl = warp_m0 + mi * 16 + (lane >> 2) + h * 8;
                int r = m0 + rl;
                if (r >= cnt) continue;
                float v1a = acc1[mi][nj][2*h],   v3a = acc3[mi][nj][2*h];
                float v1b = acc1[mi][nj][2*h+1], v3b = acc3[mi][nj][2*h+1];
                float ha = live ? (v1a / (1.f + __expf(-v1a))) * v3a : 0.f;
                float hb = live ? (v1b / (1.f + __expf(-v1b))) * v3b : 0.f;
                size_t rb = (size_t)(base + r) * KW2;
                *reinterpret_cast<__half2*>(h2_ + rb + n) = __floats2half2_rn(ha, hb);
            }
        }
    }
}

// ------- launch 5: GEMM2, CTA 128m x 128n, warp tile 64x32, 4-stage -------
__global__ __launch_bounds__(256, 2) void k_gemm2() {
    extern __shared__ char smem[];
    const int e = blockIdx.z;
    const int cnt = g_cnt[e];
    const int m0 = blockIdx.x * 128;
    if (m0 >= cnt) return;
    const int base = expert_base(e);
    const int n0g = blockIdx.y * 128;
    const int tid = threadIdx.x, wid = tid >> 5, lane = tid & 31;
    const int warp_m0 = (wid >> 2) * 64, warp_n0 = (wid & 3) * 32;

    uint32_t sb = smem_to_u32(smem);
    const __half* B = w2c + (size_t)e * D_DIM * KW2;
    const long arow = base + m0;

    // A loader: 128 rows x 4x16B; 2 cp16/thread
    const int arow_t = tid >> 1, ach = (tid & 1) * 2;
    long ar = arow + arow_t; if (ar >= TT) ar = TT - 1;
    const __half* gA = h2_ + ar * (long)KW2 + ach * 8;
    const uint32_t sdA = sb + arow_t * RSTRIDE + ach * 16;

    // B loader: 128 rows x 4x16B; 2 cp16/thread
    int nr = n0g + arow_t;           // < 1024 always
    const __half* gB = B + (long)nr * KW2 + ach * 8;
    const uint32_t sdB = sb + T128_B + arow_t * RSTRIDE + ach * 16;

    auto load_stage = [&](int st, int kc) {
        uint32_t d = st * STAGE2;
        int ko = kc * 32;
        cp16(sdA + d,      gA + ko);
        cp16(sdA + d + 16, gA + ko + 8);
        cp16(sdB + d,      gB + ko);
        cp16(sdB + d + 16, gB + ko + 8);
    };

    float acc[4][4][4] = {{{0}}};

    load_stage(0, 0); CP_COMMIT();
    load_stage(1, 1); CP_COMMIT();
    load_stage(2, 2); CP_COMMIT();

    for (int kc = 0; kc < NCH2; kc++) {
        CP_WAIT2();
        __syncthreads();
        if (kc + 3 < NCH2) load_stage((kc + 3) & 3, kc + 3);
        CP_COMMIT();
        uint32_t st = sb + (kc & 3) * STAGE2;
        uint32_t a[4][2][4];
        load_a4(st, a, warp_m0, lane);
        compute_warp4(st + T128_B, a, acc, warp_n0, lane);  // A*B
    }

#pragma unroll
    for (int mi = 0; mi < 4; mi++) {
#pragma unroll
        for (int nj = 0; nj < 4; nj++) {
            int n = n0g + warp_n0 + nj * 8 + ((lane & 3) << 1);
#pragma unroll
            for (int h = 0; h < 2; h++) {
                int rl = warp_m0 + mi * 16 + (lane >> 2) + h * 8;
                int r = m0 + rl;
                if (r >= cnt) continue;
                float2 v; v.x = acc[mi][nj][2*h]; v.y = acc[mi][nj][2*h+1];
                *reinterpret_cast<float2*>(g_y + (size_t)(base + r) * D_DIM + n) = v;
            }
        }
    }
}

// ======================= launch 6: combine =======================
__global__ void k_combine(float* __restrict__ out) {
    int i = blockIdx.x * 256 + threadIdx.x;
    int t = i >> 8, c = i & 255;
    int p0 = g_pos[2 * t], p1 = g_pos[2 * t + 1];
    float c0 = g_topp[2 * t], c1 = g_topp[2 * t + 1];
    const float4* y = reinterpret_cast<const float4*>(g_y);
    float4 a = y[(size_t)p0 * 256 + c];
    float4 b = y[(size_t)p1 * 256 + c];
    float4 o;
    o.x = c0 * a.x + c1 * b.x;  o.y = c0 * a.y + c1 * b.y;
    o.z = c0 * a.z + c1 * b.z;  o.w = c0 * a.w + c1 * b.w;
    reinterpret_cast<float4*>(out)[(size_t)t * 256 + c] = o;
}

// ======================= launch =======================
extern "C" void kernel_launch(void* const* d_in, const int* in_sizes, int n_in,
                              void* d_out, int out_size) {
    const float* x  = (const float*)d_in[0];
    const float* rw = (const float*)d_in[1];
    const float* w1 = (const float*)d_in[2];
    const float* w2 = (const float*)d_in[3];
    const float* w3 = (const float*)d_in[4];
    float* out = (float*)d_out;

    cudaFuncSetAttribute(k_gemm1, cudaFuncAttributeMaxDynamicSharedMemorySize, 4 * STAGE1);
    cudaFuncSetAttribute(k_gemm2, cudaFuncAttributeMaxDynamicSharedMemorySize, 4 * STAGE2);

    k_conv<<<CONV13_BLOCKS + CONV2_BLOCKS, 256>>>(w1, w3, w2);   // #1
    k_router<<<T_TOK / 8, 256>>>(x, rw);                          // #2
    k_scatgather<<<TT / 8, 256>>>(x, out, out_size);              // #3
    k_gemm1<<<dim3(64, 11, 8), 256, 4 * STAGE1>>>();              // #4 <- profiled
    k_gemm2<<<dim3(64, 8, 8), 256, 4 * STAGE2>>>();               // #5
    k_combine<<<T_TOK, 256>>>(out);                               // #6
}

// round 15
// speedup vs baseline: 1.0132x; 1.0132x over previous
#include <cuda_runtime.h>
#include <cuda_fp16.h>
#include <stdint.h>
#include <math.h>

#define T_TOK 8192
#define TT    16384          // 2*T gathered rows
#define D_DIM 1024
#define H_DIM 684
#define HP    704            // H padded to multiple of 64
#define NE    8
#define KW1   1024           // xg1 / w1c / w3c width (single-rounded)
#define KW2   704            // h2_ / w2c width (single-rounded)
#define NCH1  32             // K chunks (1024/32)
#define NCH2  22             // K chunks (704/32)

// ======================= scratch =======================
__device__ __half xg1[(size_t)TT * KW1];
__device__ __half w1c[(size_t)NE * H_DIM * KW1];
__device__ __half w3c[(size_t)NE * H_DIM * KW1];
__device__ __half w2c[(size_t)NE * D_DIM * KW2];
__device__ __half h2_[(size_t)TT * KW2];

__device__ int   g_rows[TT];          // gathered pos -> token
__device__ float g_comb[TT];          // gathered pos -> combine weight
__device__ int   g_cnt[NE];
__device__ int   g_cur[NE];
__device__ int   g_top[TT];
__device__ float g_topp[TT];
__device__ int   g_dcnt[NE];
__device__ float g_psum[NE];

// ======================= asm helpers (portable sm_80+) =======================
__device__ __forceinline__ uint32_t smem_to_u32(const void* p) {
    uint32_t a;
    asm("{ .reg .u64 t; cvta.to.shared.u64 t, %1; cvt.u32.u64 %0, t; }" : "=r"(a) : "l"(p));
    return a;
}

__device__ __forceinline__ void cp16(uint32_t dst, const void* src) {
    asm volatile("cp.async.cg.shared.global [%0], [%1], 16;" :: "r"(dst), "l"(src) : "memory");
}
#define CP_COMMIT() asm volatile("cp.async.commit_group;" ::: "memory")
#define CP_WAIT2()  asm volatile("cp.async.wait_group 2;" ::: "memory")

__device__ __forceinline__ void ldsm4(uint32_t* r, uint32_t addr) {
    asm volatile("ldmatrix.sync.aligned.m8n8.x4.shared.b16 {%0,%1,%2,%3}, [%4];"
                 : "=r"(r[0]), "=r"(r[1]), "=r"(r[2]), "=r"(r[3]) : "r"(addr));
}

__device__ __forceinline__ void mma16816(float* c, const uint32_t* a, uint32_t b0, uint32_t b1) {
    asm volatile("mma.sync.aligned.m16n8k16.row.col.f32.f16.f16.f32 "
                 "{%0,%1,%2,%3}, {%4,%5,%6,%7}, {%8,%9}, {%0,%1,%2,%3};"
                 : "+f"(c[0]), "+f"(c[1]), "+f"(c[2]), "+f"(c[3])
                 : "r"(a[0]), "r"(a[1]), "r"(a[2]), "r"(a[3]), "r"(b0), "r"(b1));
}

// ---- fp16 helpers ----
__device__ __forceinline__ void store4_h(__half* base, size_t o, float4 v) {
    *reinterpret_cast<__half2*>(base + o)     = __floats2half2_rn(v.x, v.y);
    *reinterpret_cast<__half2*>(base + o + 2) = __floats2half2_rn(v.z, v.w);
}

// ======================= launch 1: weight conversion + out zero + counter init ==========
#define CONV13_BLOCKS 5472   // NE*H*D/4/256
#define CONV2_BLOCKS  5632   // NE*D*176/256
__global__ void k_conv(const float* __restrict__ w1, const float* __restrict__ w3,
                       const float* __restrict__ w2, float* __restrict__ out) {
    int bx = blockIdx.x;
    int tid = threadIdx.x;
    if (bx == 0 && tid < NE) {
        g_cnt[tid] = 0; g_cur[tid] = 0;
        g_dcnt[tid] = 0; g_psum[tid] = 0.f;
    }
    // zero the main output region (aux slot written later by scatgather)
    size_t zi = (size_t)bx * 256 + tid;
    if (zi < (size_t)T_TOK * D_DIM / 4)
        reinterpret_cast<float4*>(out)[zi] = make_float4(0.f, 0.f, 0.f, 0.f);

    if (bx < CONV13_BLOCKS) {
        size_t i = (size_t)bx * 256 + tid;
        size_t row = i >> 8;
        size_t col = (i & 255) * 4;
        float4 a = reinterpret_cast<const float4*>(w1)[i];
        float4 b = reinterpret_cast<const float4*>(w3)[i];
        store4_h(w1c, row * KW1 + col, a);
        store4_h(w3c, row * KW1 + col, b);
    } else {
        size_t i = (size_t)(bx - CONV13_BLOCKS) * 256 + tid;
        size_t row = i / 176;
        int col = (int)(i % 176) * 4;
        float4 v = make_float4(0.f, 0.f, 0.f, 0.f);
        if (col < H_DIM) {
            const float* p = w2 + row * H_DIM + col;
            v.x = p[0];
            v.y = (col + 1 < H_DIM) ? p[1] : 0.f;
            v.z = (col + 2 < H_DIM) ? p[2] : 0.f;
            v.w = (col + 3 < H_DIM) ? p[3] : 0.f;
        }
        store4_h(w2c, row * KW2 + (size_t)col, v);
    }
}

// ======================= launch 2: router =======================
__global__ void k_router(const float* __restrict__ x, const float* __restrict__ rw) {
    __shared__ float s_ps[NE];
    __shared__ int   s_dc[NE];
    __shared__ int   s_cnt[NE];
    int tid = threadIdx.x;
    if (tid < NE) { s_ps[tid] = 0.f; s_dc[tid] = 0; s_cnt[tid] = 0; }
    __syncthreads();

    int warp = tid >> 5, lane = tid & 31;
    int t = blockIdx.x * 8 + warp;

    float xv[32];
    const float* xr = x + (size_t)t * D_DIM;
#pragma unroll
    for (int i = 0; i < 32; i++) xv[i] = xr[lane + 32 * i];

    float logit[NE];
#pragma unroll
    for (int e = 0; e < NE; e++) {
        const float* wr = rw + e * D_DIM;
        float s = 0.f;
#pragma unroll
        for (int i = 0; i < 32; i++) s += xv[i] * wr[lane + 32 * i];
#pragma unroll
        for (int o = 16; o; o >>= 1) s += __shfl_xor_sync(0xffffffffu, s, o);
        logit[e] = s;
    }

    if (lane == 0) {
        float mx = logit[0];
#pragma unroll
        for (int e = 1; e < NE; e++) mx = fmaxf(mx, logit[e]);
        float p[NE], sum = 0.f;
#pragma unroll
        for (int e = 0; e < NE; e++) { p[e] = expf(logit[e] - mx); sum += p[e]; }
        float inv = 1.f / sum;
#pragma unroll
        for (int e = 0; e < NE; e++) p[e] *= inv;

        int i0 = 0;
#pragma unroll
        for (int e = 1; e < NE; e++) if (p[e] > p[i0]) i0 = e;
        int i1 = (i0 == 0) ? 1 : 0;
#pragma unroll
        for (int e = 0; e < NE; e++) if (e != i0 && p[e] > p[i1]) i1 = e;

        g_top[t * 2]      = i0;    g_top[t * 2 + 1]  = i1;
        g_topp[t * 2]     = p[i0]; g_topp[t * 2 + 1] = p[i1];

        atomicAdd(&s_dc[i0], 1);
        atomicAdd(&s_cnt[i0], 1);
        atomicAdd(&s_cnt[i1], 1);
#pragma unroll
        for (int e = 0; e < NE; e++) atomicAdd(&s_ps[e], p[e]);
    }
    __syncthreads();
    if (tid < NE) {
        atomicAdd(&g_psum[tid], s_ps[tid]);
        atomicAdd(&g_dcnt[tid], s_dc[tid]);
        atomicAdd(&g_cnt[tid], s_cnt[tid]);
    }
}

// ======================= launch 3: scatter + gather (single fp16) + aux =======================
__global__ void k_scatgather(const float* __restrict__ x, float* __restrict__ out, int out_size) {
    int wid = threadIdx.x >> 5, lane = threadIdx.x & 31;
    int i = blockIdx.x * 8 + wid;            // slot id

    if (blockIdx.x == 0 && threadIdx.x == 0) {
        float s = 0.f;
        for (int e = 0; e < NE; e++)
            s += ((float)g_dcnt[e] / (float)T_TOK) * (g_psum[e] / (float)T_TOK);
        if (out_size > T_TOK * D_DIM) out[T_TOK * D_DIM] = 0.01f * s * (float)NE;
    }

    int e = g_top[i];
    int pos = 0;
    int tok = i >> 1;
    if (lane == 0) {
        int o = 0;
        for (int k = 0; k < NE; k++) { if (k == e) break; o += g_cnt[k]; }
        pos = o + atomicAdd(&g_cur[e], 1);
        g_rows[pos] = tok;
        g_comb[pos] = g_topp[i];
    }
    pos = __shfl_sync(0xffffffffu, pos, 0);

    const float4* xr = reinterpret_cast<const float4*>(x) + (size_t)tok * 256;
#pragma unroll
    for (int j = 0; j < 8; j++) {
        int c = lane + j * 32;
        store4_h(xg1, (size_t)pos * KW1 + (size_t)c * 4, xr[c]);
    }
}

__device__ __forceinline__ int expert_base(int e) {
    int o = 0;
    for (int k = 0; k < e; k++) o += g_cnt[k];
    return o;
}

// ======================= GEMM cores =======================
// 2 CTAs/SM, 256 thr (8 warps).
#define RSTRIDE  80
#define T64_B    5120            // 64 rows * 80B
#define T128_B   10240           // 128 rows * 80B
#define STAGE1   (T128_B + 2*T64_B)   // A(128m) B1(64n) B3(64n) = 20480
#define STAGE2   (2*T128_B)           // A(128m) B(128n)        = 20480

__device__ __forceinline__ void load_a(uint32_t sA, uint32_t a[2][2][4], int warp_m0, int lane) {
#pragma unroll
    for (int mi = 0; mi < 2; mi++)
#pragma unroll
        for (int kh = 0; kh < 2; kh++) {
            uint32_t ad = sA + (warp_m0 + mi*16 + (lane & 15)) * RSTRIDE
                             + (kh*16 + (lane >> 4) * 8) * 2;
            ldsm4(a[mi][kh], ad);
        }
}

// B read inline from smem (transient regs), 16 MMA  (32x32 warp tile)
__device__ __forceinline__ void compute_warp(
    uint32_t sB, const uint32_t a[2][2][4],
    float acc[2][4][4], int warp_n0, int lane)
{
#pragma unroll
    for (int nj2 = 0; nj2 < 2; nj2++) {
#pragma unroll
        for (int kh = 0; kh < 2; kh++) {
            uint32_t r[4];
            uint32_t bd = sB + (warp_n0 + nj2*16 + (lane & 15)) * RSTRIDE
                             + (kh*16 + (lane >> 4) * 8) * 2;
            ldsm4(r, bd);
            mma16816(acc[0][nj2*2 + 0], a[0][kh], r[0], r[2]);
            mma16816(acc[0][nj2*2 + 1], a[0][kh], r[1], r[3]);
            mma16816(acc[1][nj2*2 + 0], a[1][kh], r[0], r[2]);
            mma16816(acc[1][nj2*2 + 1], a[1][kh], r[1], r[3]);
        }
    }
}

// 64x32 warp tile variants (gemm2)
__device__ __forceinline__ void load_a4(uint32_t sA, uint32_t a[4][2][4], int warp_m0, int lane) {
#pragma unroll
    for (int mi = 0; mi < 4; mi++)
#pragma unroll
        for (int kh = 0; kh < 2; kh++) {
            uint32_t ad = sA + (warp_m0 + mi*16 + (lane & 15)) * RSTRIDE
                             + (kh*16 + (lane >> 4) * 8) * 2;
            ldsm4(a[mi][kh], ad);
        }
}

__device__ __forceinline__ void compute_warp4(
    uint32_t sB, const uint32_t a[4][2][4],
    float acc[4][4][4], int warp_n0, int lane)
{
#pragma unroll
    for (int nj2 = 0; nj2 < 2; nj2++) {
#pragma unroll
        for (int kh = 0; kh < 2; kh++) {
            uint32_t r[4];
            uint32_t bd = sB + (warp_n0 + nj2*16 + (lane & 15)) * RSTRIDE
                             + (kh*16 + (lane >> 4) * 8) * 2;
            ldsm4(r, bd);
#pragma unroll
            for (int mi = 0; mi < 4; mi++) {
                mma16816(acc[mi][nj2*2 + 0], a[mi][kh], r[0], r[2]);
                mma16816(acc[mi][nj2*2 + 1], a[mi][kh], r[1], r[3]);
            }
        }
    }
}

// ------- launch 4 (PROFILED): GEMM1, CTA 128m x 64n, 4m x 2n warps, 4-stage -------
__global__ __launch_bounds__(256, 2) void k_gemm1() {
    extern __shared__ char smem[];
    const int e = blockIdx.z;
    const int cnt = g_cnt[e];
    const int m0 = blockIdx.x * 128;
    if (m0 >= cnt) return;
    const int base = expert_base(e);
    const int n0g = blockIdx.y * 64;               // 11 tiles cover 704
    const int tid = threadIdx.x, wid = tid >> 5, lane = tid & 31;
    const int warp_m0 = (wid >> 1) * 32, warp_n0 = (wid & 1) * 32;

    uint32_t sb = smem_to_u32(smem);
    const __half* B1 = w1c + (size_t)e * H_DIM * KW1;
    const __half* B3 = w3c + (size_t)e * H_DIM * KW1;
    const long arow = base + m0;

    // A loader: 128 rows x 4x16B; 256 thr -> 2 cp16 each
    const int arow_t = tid >> 1, ach = (tid & 1) * 2;
    long ar = arow + arow_t; if (ar >= TT) ar = TT - 1;
    const __half* gA = xg1 + ar * (long)KW1 + ach * 8;
    const uint32_t sdA = sb + arow_t * RSTRIDE + ach * 16;

    // B loaders: 64 rows x 4x16B; 256 thr -> 1 cp16 each per tile
    const int brow = tid >> 2, bch = tid & 3;
    int nr = n0g + brow; if (nr > H_DIM - 1) nr = H_DIM - 1;
    const __half* gB1 = B1 + (long)nr * KW1 + bch * 8;
    const __half* gB3 = B3 + (long)nr * KW1 + bch * 8;
    const uint32_t sdB1 = sb + T128_B + brow * RSTRIDE + bch * 16;
    const uint32_t sdB3 = sdB1 + T64_B;

    auto load_stage = [&](int st, int kc) {
        uint32_t d = st * STAGE1;
        int ko = kc * 32;
        cp16(sdA  + d,      gA  + ko);
        cp16(sdA  + d + 16, gA  + ko + 8);
        cp16(sdB1 + d,      gB1 + ko);
        cp16(sdB3 + d,      gB3 + ko);
    };

    float acc1[2][4][4] = {{{0}}}, acc3[2][4][4] = {{{0}}};

    load_stage(0, 0); CP_COMMIT();
    load_stage(1, 1); CP_COMMIT();
    load_stage(2, 2); CP_COMMIT();

    for (int kc = 0; kc < NCH1; kc++) {
        CP_WAIT2();
        __syncthreads();
        if (kc + 3 < NCH1) load_stage((kc + 3) & 3, kc + 3);
        CP_COMMIT();
        uint32_t st = sb + (kc & 3) * STAGE1;
        uint32_t a[2][2][4];
        load_a(st, a, warp_m0, lane);
        compute_warp(st + T128_B,         a, acc1, warp_n0, lane); // A*B1
        compute_warp(st + T128_B + T64_B, a, acc3, warp_n0, lane); // A*B3
    }

    // epilogue: swiglu -> single fp16 h
#pragma unroll
    for (int mi = 0; mi < 2; mi++) {
#pragma unroll
        for (int nj = 0; nj < 4; nj++) {
            int n = n0g + warp_n0 + nj * 8 + ((lane & 3) << 1);
            if (n >= HP) continue;
            bool live = (n < H_DIM);
#pragma unroll
            for (int h = 0; h < 2; h++) {
                int rl = warp_m0 + mi * 16 + (lane >> 2) + h * 8;
                int r = m0 + rl;
                if (r >= cnt) continue;
                float v1a = acc1[mi][nj][2*h],   v3a = acc3[mi][nj][2*h];
                float v1b = acc1[mi][nj][2*h+1], v3b = acc3[mi][nj][2*h+1];
                float ha = live ? (v1a / (1.f + __expf(-v1a))) * v3a : 0.f;
                float hb = live ? (v1b / (1.f + __expf(-v1b))) * v3b : 0.f;
                size_t rb = (size_t)(base + r) * KW2;
                *reinterpret_cast<__half2*>(h2_ + rb + n) = __floats2half2_rn(ha, hb);
            }
        }
    }
}

// ------- launch 5: GEMM2 + fused combine, CTA 128m x 128n, warp tile 64x32 -------
__global__ __launch_bounds__(256, 2) void k_gemm2(float* __restrict__ out) {
    extern __shared__ char smem[];
    const int e = blockIdx.z;
    const int cnt = g_cnt[e];
    const int m0 = blockIdx.x * 128;
    if (m0 >= cnt) return;
    const int base = expert_base(e);
    const int n0g = blockIdx.y * 128;
    const int tid = threadIdx.x, wid = tid >> 5, lane = tid & 31;
    const int warp_m0 = (wid >> 2) * 64, warp_n0 = (wid & 3) * 32;

    uint32_t sb = smem_to_u32(smem);
    const __half* B = w2c + (size_t)e * D_DIM * KW2;
    const long arow = base + m0;

    // A loader: 128 rows x 4x16B; 2 cp16/thread
    const int arow_t = tid >> 1, ach = (tid & 1) * 2;
    long ar = arow + arow_t; if (ar >= TT) ar = TT - 1;
    const __half* gA = h2_ + ar * (long)KW2 + ach * 8;
    const uint32_t sdA = sb + arow_t * RSTRIDE + ach * 16;

    // B loader: 128 rows x 4x16B; 2 cp16/thread
    int nr = n0g + arow_t;           // < 1024 always
    const __half* gB = B + (long)nr * KW2 + ach * 8;
    const uint32_t sdB = sb + T128_B + arow_t * RSTRIDE + ach * 16;

    auto load_stage = [&](int st, int kc) {
        uint32_t d = st * STAGE2;
        int ko = kc * 32;
        cp16(sdA + d,      gA + ko);
        cp16(sdA + d + 16, gA + ko + 8);
        cp16(sdB + d,      gB + ko);
        cp16(sdB + d + 16, gB + ko + 8);
    };

    float acc[4][4][4] = {{{0}}};

    load_stage(0, 0); CP_COMMIT();
    load_stage(1, 1); CP_COMMIT();
    load_stage(2, 2); CP_COMMIT();

    for (int kc = 0; kc < NCH2; kc++) {
        CP_WAIT2();
        __syncthreads();
        if (kc + 3 < NCH2) load_stage((kc + 3) & 3, kc + 3);
        CP_COMMIT();
        uint32_t st = sb + (kc & 3) * STAGE2;
        uint32_t a[4][2][4];
        load_a4(st, a, warp_m0, lane);
        compute_warp4(st + T128_B, a, acc, warp_n0, lane);  // A*B
    }

    // fused combine epilogue: out[tok] += comb * y  (exactly 2 adds per element)
#pragma unroll
    for (int mi = 0; mi < 4; mi++) {
#pragma unroll
        for (int h = 0; h < 2; h++) {
            int rl = warp_m0 + mi * 16 + (lane >> 2) + h * 8;
            int r = m0 + rl;
            if (r >= cnt) continue;
            int tok = g_rows[base + r];
            float cw = g_comb[base + r];
            float* orow = out + (size_t)tok * D_DIM;
#pragma unroll
            for (int nj = 0; nj < 4; nj++) {
                int n = n0g + warp_n0 + nj * 8 + ((lane & 3) << 1);
                atomicAdd(&orow[n],     acc[mi][nj][2*h]     * cw);
                atomicAdd(&orow[n + 1], acc[mi][nj][2*h + 1] * cw);
            }
        }
    }
}

// ======================= launch =======================
extern "C" void kernel_launch(void* const* d_in, const int* in_sizes, int n_in,
                              void* d_out, int out_size) {
    const float* x  = (const float*)d_in[0];
    const float* rw = (const float*)d_in[1];
    const float* w1 = (const float*)d_in[2];
    const float* w2 = (const float*)d_in[3];
    const float* w3 = (const float*)d_in[4];
    float* out = (float*)d_out;

    cudaFuncSetAttribute(k_gemm1, cudaFuncAttributeMaxDynamicSharedMemorySize, 4 * STAGE1);
    cudaFuncSetAttribute(k_gemm2, cudaFuncAttributeMaxDynamicSharedMemorySize, 4 * STAGE2);

    k_conv<<<CONV13_BLOCKS + CONV2_BLOCKS, 256>>>(w1, w3, w2, out);  // #1
    k_router<<<T_TOK / 8, 256>>>(x, rw);                              // #2
    k_scatgather<<<TT / 8, 256>>>(x, out, out_size);                  // #3
    k_gemm1<<<dim3(64, 11, 8), 256, 4 * STAGE1>>>();                  // #4 <- profiled
    k_gemm2<<<dim3(64, 8, 8), 256, 4 * STAGE2>>>(out);                // #5
}

// round 16
// speedup vs baseline: 1.0566x; 1.0428x over previous
#include <cuda_runtime.h>
#include <cuda_fp16.h>
#include <stdint.h>
#include <math.h>

#define T_TOK 8192
#define TT    16384          // 2*T gathered rows
#define D_DIM 1024
#define H_DIM 684
#define HP    704            // H padded to multiple of 64
#define NE    8
#define KW1   1024           // xg1 / w1c / w3c width (single-rounded)
#define KW2   704            // h2_ / w2c width (single-rounded)
#define NCH1  32             // K chunks (1024/32)
#define NCH2  22             // K chunks (704/32)

// ======================= scratch =======================
__device__ __half xg1[(size_t)TT * KW1];
__device__ __half w1c[(size_t)NE * H_DIM * KW1];
__device__ __half w3c[(size_t)NE * H_DIM * KW1];
__device__ __half w2c[(size_t)NE * D_DIM * KW2];
__device__ __half h2_[(size_t)TT * KW2];

__device__ int   g_rows[TT];          // gathered pos -> token
__device__ float g_comb[TT];          // gathered pos -> combine weight
__device__ int   g_cnt[NE];
__device__ int   g_cur[NE];
__device__ int   g_top[TT];
__device__ float g_topp[TT];
__device__ int   g_dcnt[NE];
__device__ float g_psum[NE];

// ======================= asm helpers (portable sm_80+) =======================
__device__ __forceinline__ uint32_t smem_to_u32(const void* p) {
    uint32_t a;
    asm("{ .reg .u64 t; cvta.to.shared.u64 t, %1; cvt.u32.u64 %0, t; }" : "=r"(a) : "l"(p));
    return a;
}

__device__ __forceinline__ void cp16(uint32_t dst, const void* src) {
    asm volatile("cp.async.cg.shared.global [%0], [%1], 16;" :: "r"(dst), "l"(src) : "memory");
}
#define CP_COMMIT() asm volatile("cp.async.commit_group;" ::: "memory")
#define CP_WAIT2()  asm volatile("cp.async.wait_group 2;" ::: "memory")

__device__ __forceinline__ void ldsm4(uint32_t* r, uint32_t addr) {
    asm volatile("ldmatrix.sync.aligned.m8n8.x4.shared.b16 {%0,%1,%2,%3}, [%4];"
                 : "=r"(r[0]), "=r"(r[1]), "=r"(r[2]), "=r"(r[3]) : "r"(addr));
}

__device__ __forceinline__ void mma16816(float* c, const uint32_t* a, uint32_t b0, uint32_t b1) {
    asm volatile("mma.sync.aligned.m16n8k16.row.col.f32.f16.f16.f32 "
                 "{%0,%1,%2,%3}, {%4,%5,%6,%7}, {%8,%9}, {%0,%1,%2,%3};"
                 : "+f"(c[0]), "+f"(c[1]), "+f"(c[2]), "+f"(c[3])
                 : "r"(a[0]), "r"(a[1]), "r"(a[2]), "r"(a[3]), "r"(b0), "r"(b1));
}

// ---- fp16 helpers ----
__device__ __forceinline__ void store4_h(__half* base, size_t o, float4 v) {
    *reinterpret_cast<__half2*>(base + o)     = __floats2half2_rn(v.x, v.y);
    *reinterpret_cast<__half2*>(base + o + 2) = __floats2half2_rn(v.z, v.w);
}

// ======================= launch 0: counter init =======================
__global__ void k_init0() {
    int i = threadIdx.x;
    if (i < NE) { g_cnt[i] = 0; g_cur[i] = 0; g_dcnt[i] = 0; g_psum[i] = 0.f; }
}

// ======================= launch 1: conv + router (merged) + out zero =======================
#define CONV13_BLOCKS 5472   // NE*H*D/4/256
#define CONV2_BLOCKS  5632   // NE*D*176/256
#define ROUTER_BLOCKS 1024   // T_TOK/8
__global__ void k_convrouter(const float* __restrict__ w1, const float* __restrict__ w3,
                             const float* __restrict__ w2, const float* __restrict__ x,
                             const float* __restrict__ rw, float* __restrict__ out) {
    int bx = blockIdx.x;
    int tid = threadIdx.x;

    // zero the main output region (first 8192 blocks cover T*D/4 float4s)
    size_t zi = (size_t)bx * 256 + tid;
    if (zi < (size_t)T_TOK * D_DIM / 4)
        reinterpret_cast<float4*>(out)[zi] = make_float4(0.f, 0.f, 0.f, 0.f);

    if (bx < CONV13_BLOCKS) {
        size_t i = (size_t)bx * 256 + tid;
        size_t row = i >> 8;
        size_t col = (i & 255) * 4;
        float4 a = reinterpret_cast<const float4*>(w1)[i];
        float4 b = reinterpret_cast<const float4*>(w3)[i];
        store4_h(w1c, row * KW1 + col, a);
        store4_h(w3c, row * KW1 + col, b);
        return;
    }
    if (bx < CONV13_BLOCKS + CONV2_BLOCKS) {
        size_t i = (size_t)(bx - CONV13_BLOCKS) * 256 + tid;
        size_t row = i / 176;
        int col = (int)(i % 176) * 4;
        float4 v = make_float4(0.f, 0.f, 0.f, 0.f);
        if (col < H_DIM) {
            const float* p = w2 + row * H_DIM + col;
            v.x = p[0];
            v.y = (col + 1 < H_DIM) ? p[1] : 0.f;
            v.z = (col + 2 < H_DIM) ? p[2] : 0.f;
            v.w = (col + 3 < H_DIM) ? p[3] : 0.f;
        }
        store4_h(w2c, row * KW2 + (size_t)col, v);
        return;
    }

    // ---- router part ----
    int rbx = bx - (CONV13_BLOCKS + CONV2_BLOCKS);
    __shared__ float s_ps[NE];
    __shared__ int   s_dc[NE];
    __shared__ int   s_cnt[NE];
    if (tid < NE) { s_ps[tid] = 0.f; s_dc[tid] = 0; s_cnt[tid] = 0; }
    __syncthreads();

    int warp = tid >> 5, lane = tid & 31;
    int t = rbx * 8 + warp;

    float xv[32];
    const float* xr = x + (size_t)t * D_DIM;
#pragma unroll
    for (int i = 0; i < 32; i++) xv[i] = xr[lane + 32 * i];

    float logit[NE];
#pragma unroll
    for (int e = 0; e < NE; e++) {
        const float* wr = rw + e * D_DIM;
        float s = 0.f;
#pragma unroll
        for (int i = 0; i < 32; i++) s += xv[i] * wr[lane + 32 * i];
#pragma unroll
        for (int o = 16; o; o >>= 1) s += __shfl_xor_sync(0xffffffffu, s, o);
        logit[e] = s;
    }

    if (lane == 0) {
        float mx = logit[0];
#pragma unroll
        for (int e = 1; e < NE; e++) mx = fmaxf(mx, logit[e]);
        float p[NE], sum = 0.f;
#pragma unroll
        for (int e = 0; e < NE; e++) { p[e] = expf(logit[e] - mx); sum += p[e]; }
        float inv = 1.f / sum;
#pragma unroll
        for (int e = 0; e < NE; e++) p[e] *= inv;

        int i0 = 0;
#pragma unroll
        for (int e = 1; e < NE; e++) if (p[e] > p[i0]) i0 = e;
        int i1 = (i0 == 0) ? 1 : 0;
#pragma unroll
        for (int e = 0; e < NE; e++) if (e != i0 && p[e] > p[i1]) i1 = e;

        g_top[t * 2]      = i0;    g_top[t * 2 + 1]  = i1;
        g_topp[t * 2]     = p[i0]; g_topp[t * 2 + 1] = p[i1];

        atomicAdd(&s_dc[i0], 1);
        atomicAdd(&s_cnt[i0], 1);
        atomicAdd(&s_cnt[i1], 1);
#pragma unroll
        for (int e = 0; e < NE; e++) atomicAdd(&s_ps[e], p[e]);
    }
    __syncthreads();
    if (tid < NE) {
        atomicAdd(&g_psum[tid], s_ps[tid]);
        atomicAdd(&g_dcnt[tid], s_dc[tid]);
        atomicAdd(&g_cnt[tid], s_cnt[tid]);
    }
}

// ======================= launch 2: scatter + gather (single fp16) + aux =======================
__global__ void k_scatgather(const float* __restrict__ x, float* __restrict__ out, int out_size) {
    int wid = threadIdx.x >> 5, lane = threadIdx.x & 31;
    int i = blockIdx.x * 8 + wid;            // slot id

    if (blockIdx.x == 0 && threadIdx.x == 0) {
        float s = 0.f;
        for (int e = 0; e < NE; e++)
            s += ((float)g_dcnt[e] / (float)T_TOK) * (g_psum[e] / (float)T_TOK);
        if (out_size > T_TOK * D_DIM) out[T_TOK * D_DIM] = 0.01f * s * (float)NE;
    }

    int e = g_top[i];
    int pos = 0;
    int tok = i >> 1;
    if (lane == 0) {
        int o = 0;
        for (int k = 0; k < NE; k++) { if (k == e) break; o += g_cnt[k]; }
        pos = o + atomicAdd(&g_cur[e], 1);
        g_rows[pos] = tok;
        g_comb[pos] = g_topp[i];
    }
    pos = __shfl_sync(0xffffffffu, pos, 0);

    const float4* xr = reinterpret_cast<const float4*>(x) + (size_t)tok * 256;
#pragma unroll
    for (int j = 0; j < 8; j++) {
        int c = lane + j * 32;
        store4_h(xg1, (size_t)pos * KW1 + (size_t)c * 4, xr[c]);
    }
}

__device__ __forceinline__ int expert_base(int e) {
    int o = 0;
    for (int k = 0; k < e; k++) o += g_cnt[k];
    return o;
}

// ======================= GEMM cores =======================
// 2 CTAs/SM, 256 thr (8 warps).
#define RSTRIDE  80
#define T64_B    5120            // 64 rows * 80B
#define T128_B   10240           // 128 rows * 80B
#define STAGE1   (T128_B + 2*T64_B)   // A(128m) B1(64n) B3(64n) = 20480
#define STAGE2   (2*T128_B)           // A(128m) B(128n)        = 20480

__device__ __forceinline__ void load_a(uint32_t sA, uint32_t a[2][2][4], int warp_m0, int lane) {
#pragma unroll
    for (int mi = 0; mi < 2; mi++)
#pragma unroll
        for (int kh = 0; kh < 2; kh++) {
            uint32_t ad = sA + (warp_m0 + mi*16 + (lane & 15)) * RSTRIDE
                             + (kh*16 + (lane >> 4) * 8) * 2;
            ldsm4(a[mi][kh], ad);
        }
}

// B read inline from smem (transient regs), 16 MMA  (32x32 warp tile)
__device__ __forceinline__ void compute_warp(
    uint32_t sB, const uint32_t a[2][2][4],
    float acc[2][4][4], int warp_n0, int lane)
{
#pragma unroll
    for (int nj2 = 0; nj2 < 2; nj2++) {
#pragma unroll
        for (int kh = 0; kh < 2; kh++) {
            uint32_t r[4];
            uint32_t bd = sB + (warp_n0 + nj2*16 + (lane & 15)) * RSTRIDE
                             + (kh*16 + (lane >> 4) * 8) * 2;
            ldsm4(r, bd);
            mma16816(acc[0][nj2*2 + 0], a[0][kh], r[0], r[2]);
            mma16816(acc[0][nj2*2 + 1], a[0][kh], r[1], r[3]);
            mma16816(acc[1][nj2*2 + 0], a[1][kh], r[0], r[2]);
            mma16816(acc[1][nj2*2 + 1], a[1][kh], r[1], r[3]);
        }
    }
}

// 64x32 warp tile variants (gemm2)
__device__ __forceinline__ void load_a4(uint32_t sA, uint32_t a[4][2][4], int warp_m0, int lane) {
#pragma unroll
    for (int mi = 0; mi < 4; mi++)
#pragma unroll
        for (int kh = 0; kh < 2; kh++) {
            uint32_t ad = sA + (warp_m0 + mi*16 + (lane & 15)) * RSTRIDE
                             + (kh*16 + (lane >> 4) * 8) * 2;
            ldsm4(a[mi][kh], ad);
        }
}

__device__ __forceinline__ void compute_warp4(
    uint32_t sB, const uint32_t a[4][2][4],
    float acc[4][4][4], int warp_n0, int lane)
{
#pragma unroll
    for (int nj2 = 0; nj2 < 2; nj2++) {
#pragma unroll
        for (int kh = 0; kh < 2; kh++) {
            uint32_t r[4];
            uint32_t bd = sB + (warp_n0 + nj2*16 + (lane & 15)) * RSTRIDE
                             + (kh*16 + (lane >> 4) * 8) * 2;
            ldsm4(r, bd);
#pragma unroll
            for (int mi = 0; mi < 4; mi++) {
                mma16816(acc[mi][nj2*2 + 0], a[mi][kh], r[0], r[2]);
                mma16816(acc[mi][nj2*2 + 1], a[mi][kh], r[1], r[3]);
            }
        }
    }
}

// ------- launch 3 (PROFILED): GEMM1, CTA 128m x 64n, 4m x 2n warps, 4-stage -------
__global__ __launch_bounds__(256, 2) void k_gemm1() {
    extern __shared__ char smem[];
    const int e = blockIdx.z;
    const int cnt = g_cnt[e];
    const int m0 = blockIdx.x * 128;
    if (m0 >= cnt) return;
    const int base = expert_base(e);
    const int n0g = blockIdx.y * 64;               // 11 tiles cover 704
    const int tid = threadIdx.x, wid = tid >> 5, lane = tid & 31;
    const int warp_m0 = (wid >> 1) * 32, warp_n0 = (wid & 1) * 32;

    uint32_t sb = smem_to_u32(smem);
    const __half* B1 = w1c + (size_t)e * H_DIM * KW1;
    const __half* B3 = w3c + (size_t)e * H_DIM * KW1;
    const long arow = base + m0;

    // A loader: 128 rows x 4x16B; 256 thr -> 2 cp16 each
    const int arow_t = tid >> 1, ach = (tid & 1) * 2;
    long ar = arow + arow_t; if (ar >= TT) ar = TT - 1;
    const __half* gA = xg1 + ar * (long)KW1 + ach * 8;
    const uint32_t sdA = sb + arow_t * RSTRIDE + ach * 16;

    // B loaders: 64 rows x 4x16B; 256 thr -> 1 cp16 each per tile
    const int brow = tid >> 2, bch = tid & 3;
    int nr = n0g + brow; if (nr > H_DIM - 1) nr = H_DIM - 1;
    const __half* gB1 = B1 + (long)nr * KW1 + bch * 8;
    const __half* gB3 = B3 + (long)nr * KW1 + bch * 8;
    const uint32_t sdB1 = sb + T128_B + brow * RSTRIDE + bch * 16;
    const uint32_t sdB3 = sdB1 + T64_B;

    auto load_stage = [&](int st, int kc) {
        uint32_t d = st * STAGE1;
        int ko = kc * 32;
        cp16(sdA  + d,      gA  + ko);
        cp16(sdA  + d + 16, gA  + ko + 8);
        cp16(sdB1 + d,      gB1 + ko);
        cp16(sdB3 + d,      gB3 + ko);
    };

    float acc1[2][4][4] = {{{0}}}, acc3[2][4][4] = {{{0}}};

    load_stage(0, 0); CP_COMMIT();
    load_stage(1, 1); CP_COMMIT();
    load_stage(2, 2); CP_COMMIT();

#pragma unroll 4
    for (int kc = 0; kc < NCH1; kc++) {
        CP_WAIT2();
        __syncthreads();
        if (kc + 3 < NCH1) load_stage((kc + 3) & 3, kc + 3);
        CP_COMMIT();
        uint32_t st = sb + (kc & 3) * STAGE1;
        uint32_t a[2][2][4];
        load_a(st, a, warp_m0, lane);
        compute_warp(st + T128_B,         a, acc1, warp_n0, lane); // A*B1
        compute_warp(st + T128_B + T64_B, a, acc3, warp_n0, lane); // A*B3
    }

    // epilogue: swiglu -> single fp16 h
#pragma unroll
    for (int mi = 0; mi < 2; mi++) {
#pragma unroll
        for (int nj = 0; nj < 4; nj++) {
            int n = n0g + warp_n0 + nj * 8 + ((lane & 3) << 1);
            if (n >= HP) continue;
            bool live = (n < H_DIM);
#pragma unroll
            for (int h = 0; h < 2; h++) {
                int rl = warp_m0 + mi * 16 + (lane >> 2) + h * 8;
                int r = m0 + rl;
                if (r >= cnt) continue;
                float v1a = acc1[mi][nj][2*h],   v3a = acc3[mi][nj][2*h];
                float v1b = acc1[mi][nj][2*h+1], v3b = acc3[mi][nj][2*h+1];
                float ha = live ? (v1a / (1.f + __expf(-v1a))) * v3a : 0.f;
                float hb = live ? (v1b / (1.f + __expf(-v1b))) * v3b : 0.f;
                size_t rb = (size_t)(base + r) * KW2;
                *reinterpret_cast<__half2*>(h2_ + rb + n) = __floats2half2_rn(ha, hb);
            }
        }
    }
}

// ------- launch 4: GEMM2 + fused combine, CTA 128m x 128n, warp tile 64x32 -------
__global__ __launch_bounds__(256, 2) void k_gemm2(float* __restrict__ out) {
    extern __shared__ char smem[];
    const int e = blockIdx.z;
    const int cnt = g_cnt[e];
    const int m0 = blockIdx.x * 128;
    if (m0 >= cnt) return;
    const int base = expert_base(e);
    const int n0g = blockIdx.y * 128;
    const int tid = threadIdx.x, wid = tid >> 5, lane = tid & 31;
    const int warp_m0 = (wid >> 2) * 64, warp_n0 = (wid & 3) * 32;

    uint32_t sb = smem_to_u32(smem);
    const __half* B = w2c + (size_t)e * D_DIM * KW2;
    const long arow = base + m0;

    // A loader: 128 rows x 4x16B; 2 cp16/thread
    const int arow_t = tid >> 1, ach = (tid & 1) * 2;
    long ar = arow + arow_t; if (ar >= TT) ar = TT - 1;
    const __half* gA = h2_ + ar * (long)KW2 + ach * 8;
    const uint32_t sdA = sb + arow_t * RSTRIDE + ach * 16;

    // B loader: 128 rows x 4x16B; 2 cp16/thread
    int nr = n0g + arow_t;           // < 1024 always
    const __half* gB = B + (long)nr * KW2 + ach * 8;
    const uint32_t sdB = sb + T128_B + arow_t * RSTRIDE + ach * 16;

    auto load_stage = [&](int st, int kc) {
        uint32_t d = st * STAGE2;
        int ko = kc * 32;
        cp16(sdA + d,      gA + ko);
        cp16(sdA + d + 16, gA + ko + 8);
        cp16(sdB + d,      gB + ko);
        cp16(sdB + d + 16, gB + ko + 8);
    };

    float acc[4][4][4] = {{{0}}};

    load_stage(0, 0); CP_COMMIT();
    load_stage(1, 1); CP_COMMIT();
    load_stage(2, 2); CP_COMMIT();

#pragma unroll 2
    for (int kc = 0; kc < NCH2; kc++) {
        CP_WAIT2();
        __syncthreads();
        if (kc + 3 < NCH2) load_stage((kc + 3) & 3, kc + 3);
        CP_COMMIT();
        uint32_t st = sb + (kc & 3) * STAGE2;
        uint32_t a[4][2][4];
        load_a4(st, a, warp_m0, lane);
        compute_warp4(st + T128_B, a, acc, warp_n0, lane);  // A*B
    }

    // fused combine epilogue: out[tok] += comb * y  (exactly 2 adds per element)
#pragma unroll
    for (int mi = 0; mi < 4; mi++) {
#pragma unroll
        for (int h = 0; h < 2; h++) {
            int rl = warp_m0 + mi * 16 + (lane >> 2) + h * 8;
            int r = m0 + rl;
            if (r >= cnt) continue;
            int tok = g_rows[base + r];
            float cw = g_comb[base + r];
            float* orow = out + (size_t)tok * D_DIM;
#pragma unroll
            for (int nj = 0; nj < 4; nj++) {
                int n = n0g + warp_n0 + nj * 8 + ((lane & 3) << 1);
                atomicAdd(&orow[n],     acc[mi][nj][2*h]     * cw);
                atomicAdd(&orow[n + 1], acc[mi][nj][2*h + 1] * cw);
            }
        }
    }
}

// ======================= launch =======================
extern "C" void kernel_launch(void* const* d_in, const int* in_sizes, int n_in,
                              void* d_out, int out_size) {
    const float* x  = (const float*)d_in[0];
    const float* rw = (const float*)d_in[1];
    const float* w1 = (const float*)d_in[2];
    const float* w2 = (const float*)d_in[3];
    const float* w3 = (const float*)d_in[4];
    float* out = (float*)d_out;

    cudaFuncSetAttribute(k_gemm1, cudaFuncAttributeMaxDynamicSharedMemorySize, 4 * STAGE1);
    cudaFuncSetAttribute(k_gemm2, cudaFuncAttributeMaxDynamicSharedMemorySize, 4 * STAGE2);

    k_init0<<<1, 32>>>();                                                        // #1
    k_convrouter<<<CONV13_BLOCKS + CONV2_BLOCKS + ROUTER_BLOCKS, 256>>>(
        w1, w3, w2, x, rw, out);                                                 // #2
    k_scatgather<<<TT / 8, 256>>>(x, out, out_size);                             // #3
    k_gemm1<<<dim3(64, 11, 8), 256, 4 * STAGE1>>>();                             // #4 <- profiled
    k_gemm2<<<dim3(64, 8, 8), 256, 4 * STAGE2>>>(out);                           // #5
}

// round 17
// speedup vs baseline: 1.0756x; 1.0180x over previous
#include <cuda_runtime.h>
#include <cuda_fp16.h>
#include <stdint.h>
#include <math.h>

#define T_TOK 8192
#define TT    16384
#define D_DIM 1024
#define H_DIM 684
#define HP    704            // H padded to multiple of 64
#define NE    8
#define ECAP  8192           // fixed per-expert row capacity (cnt_e <= 8192)
#define KW1   1024           // xg1 / w1c / w3c width (single-rounded fp16)
#define KW2   704            // h2_ / w2c width (single-rounded fp16)
#define NCH1  32             // K chunks (1024/32)
#define NCH2  22             // K chunks (704/32)

// ======================= scratch =======================
__device__ __half xg1[(size_t)NE * ECAP * KW1];
__device__ __half w1c[(size_t)NE * H_DIM * KW1];
__device__ __half w3c[(size_t)NE * H_DIM * KW1];
__device__ __half w2c[(size_t)NE * D_DIM * KW2];
__device__ __half h2_[(size_t)NE * ECAP * KW2];

__device__ int   g_rows[(size_t)NE * ECAP];   // slot pos -> token
__device__ float g_comb[(size_t)NE * ECAP];   // slot pos -> combine weight
__device__ int   g_cnt[NE];
__device__ int   g_dcnt[NE];
__device__ float g_psum[NE];

// ======================= asm helpers (portable sm_80+) =======================
__device__ __forceinline__ uint32_t smem_to_u32(const void* p) {
    uint32_t a;
    asm("{ .reg .u64 t; cvta.to.shared.u64 t, %1; cvt.u32.u64 %0, t; }" : "=r"(a) : "l"(p));
    return a;
}

__device__ __forceinline__ void cp16(uint32_t dst, const void* src) {
    asm volatile("cp.async.cg.shared.global [%0], [%1], 16;" :: "r"(dst), "l"(src) : "memory");
}
#define CP_COMMIT() asm volatile("cp.async.commit_group;" ::: "memory")
#define CP_WAIT2()  asm volatile("cp.async.wait_group 2;" ::: "memory")

__device__ __forceinline__ void ldsm4(uint32_t* r, uint32_t addr) {
    asm volatile("ldmatrix.sync.aligned.m8n8.x4.shared.b16 {%0,%1,%2,%3}, [%4];"
                 : "=r"(r[0]), "=r"(r[1]), "=r"(r[2]), "=r"(r[3]) : "r"(addr));
}

__device__ __forceinline__ void mma16816(float* c, const uint32_t* a, uint32_t b0, uint32_t b1) {
    asm volatile("mma.sync.aligned.m16n8k16.row.col.f32.f16.f16.f32 "
                 "{%0,%1,%2,%3}, {%4,%5,%6,%7}, {%8,%9}, {%0,%1,%2,%3};"
                 : "+f"(c[0]), "+f"(c[1]), "+f"(c[2]), "+f"(c[3])
                 : "r"(a[0]), "r"(a[1]), "r"(a[2]), "r"(a[3]), "r"(b0), "r"(b1));
}

// ---- fp16 helpers ----
__device__ __forceinline__ void store4_h(__half* base, size_t o, float4 v) {
    *reinterpret_cast<__half2*>(base + o)     = __floats2half2_rn(v.x, v.y);
    *reinterpret_cast<__half2*>(base + o + 2) = __floats2half2_rn(v.z, v.w);
}

// ======================= launch 0: counter init =======================
__global__ void k_init0() {
    int i = threadIdx.x;
    if (i < NE) { g_cnt[i] = 0; g_dcnt[i] = 0; g_psum[i] = 0.f; }
}

// ======================= launch 1: conv + router + scatter/gather (fully fused) ==========
#define CONV13_BLOCKS 5472   // NE*H*D/4/256
#define CONV2_BLOCKS  5632   // NE*D*176/256
#define ROUTER_BLOCKS 1024   // T_TOK/8
__global__ void k_main(const float* __restrict__ w1, const float* __restrict__ w3,
                       const float* __restrict__ w2, const float* __restrict__ x,
                       const float* __restrict__ rw, float* __restrict__ out) {
    int bx = blockIdx.x;
    int tid = threadIdx.x;

    // zero the main output region (first 8192 blocks cover T*D/4 float4s)
    size_t zi = (size_t)bx * 256 + tid;
    if (zi < (size_t)T_TOK * D_DIM / 4)
        reinterpret_cast<float4*>(out)[zi] = make_float4(0.f, 0.f, 0.f, 0.f);

    if (bx < CONV13_BLOCKS) {
        size_t i = (size_t)bx * 256 + tid;
        size_t row = i >> 8;
        size_t col = (i & 255) * 4;
        float4 a = reinterpret_cast<const float4*>(w1)[i];
        float4 b = reinterpret_cast<const float4*>(w3)[i];
        store4_h(w1c, row * KW1 + col, a);
        store4_h(w3c, row * KW1 + col, b);
        return;
    }
    if (bx < CONV13_BLOCKS + CONV2_BLOCKS) {
        size_t i = (size_t)(bx - CONV13_BLOCKS) * 256 + tid;
        size_t row = i / 176;
        int col = (int)(i % 176) * 4;
        float4 v = make_float4(0.f, 0.f, 0.f, 0.f);
        if (col < H_DIM) {
            const float* p = w2 + row * H_DIM + col;
            v.x = p[0];
            v.y = (col + 1 < H_DIM) ? p[1] : 0.f;
            v.z = (col + 2 < H_DIM) ? p[2] : 0.f;
            v.w = (col + 3 < H_DIM) ? p[3] : 0.f;
        }
        store4_h(w2c, row * KW2 + (size_t)col, v);
        return;
    }

    // ---- router + scatter + gather ----
    int rbx = bx - (CONV13_BLOCKS + CONV2_BLOCKS);
    __shared__ float s_ps[NE];
    __shared__ int   s_dc[NE];
    if (tid < NE) { s_ps[tid] = 0.f; s_dc[tid] = 0; }
    __syncthreads();

    int warp = tid >> 5, lane = tid & 31;
    int t = rbx * 8 + warp;

    float xv[32];
    const float* xr = x + (size_t)t * D_DIM;
#pragma unroll
    for (int i = 0; i < 32; i++) xv[i] = xr[lane + 32 * i];

    float logit[NE];
#pragma unroll
    for (int e = 0; e < NE; e++) {
        const float* wr = rw + e * D_DIM;
        float s = 0.f;
#pragma unroll
        for (int i = 0; i < 32; i++) s += xv[i] * wr[lane + 32 * i];
#pragma unroll
        for (int o = 16; o; o >>= 1) s += __shfl_xor_sync(0xffffffffu, s, o);
        logit[e] = s;
    }

    int pos0 = 0, pos1 = 0;
    if (lane == 0) {
        float mx = logit[0];
#pragma unroll
        for (int e = 1; e < NE; e++) mx = fmaxf(mx, logit[e]);
        float p[NE], sum = 0.f;
#pragma unroll
        for (int e = 0; e < NE; e++) { p[e] = expf(logit[e] - mx); sum += p[e]; }
        float inv = 1.f / sum;
#pragma unroll
        for (int e = 0; e < NE; e++) p[e] *= inv;

        int i0 = 0;
#pragma unroll
        for (int e = 1; e < NE; e++) if (p[e] > p[i0]) i0 = e;
        int i1 = (i0 == 0) ? 1 : 0;
#pragma unroll
        for (int e = 0; e < NE; e++) if (e != i0 && p[e] > p[i1]) i1 = e;

        pos0 = i0 * ECAP + atomicAdd(&g_cnt[i0], 1);
        pos1 = i1 * ECAP + atomicAdd(&g_cnt[i1], 1);
        g_rows[pos0] = t;  g_comb[pos0] = p[i0];
        g_rows[pos1] = t;  g_comb[pos1] = p[i1];

        atomicAdd(&s_dc[i0], 1);
#pragma unroll
        for (int e = 0; e < NE; e++) atomicAdd(&s_ps[e], p[e]);
    }
    pos0 = __shfl_sync(0xffffffffu, pos0, 0);
    pos1 = __shfl_sync(0xffffffffu, pos1, 0);

    // gather: write x row (fp16 single-rounded) to both slot positions
    const float4* xr4 = reinterpret_cast<const float4*>(xr);
#pragma unroll
    for (int j = 0; j < 8; j++) {
        int c = lane + j * 32;
        float4 v = xr4[c];
        store4_h(xg1, (size_t)pos0 * KW1 + (size_t)c * 4, v);
        store4_h(xg1, (size_t)pos1 * KW1 + (size_t)c * 4, v);
    }

    __syncthreads();
    if (tid < NE) {
        atomicAdd(&g_psum[tid], s_ps[tid]);
        atomicAdd(&g_dcnt[tid], s_dc[tid]);
    }
}

// ======================= GEMM cores =======================
// 2 CTAs/SM, 256 thr (8 warps).
#define RSTRIDE  80
#define T64_B    5120            // 64 rows * 80B
#define T128_B   10240           // 128 rows * 80B
#define STAGE1   (T128_B + 2*T64_B)   // A(128m) B1(64n) B3(64n) = 20480
#define STAGE2   (2*T128_B)           // A(128m) B(128n)        = 20480

__device__ __forceinline__ void load_a(uint32_t sA, uint32_t a[2][2][4], int warp_m0, int lane) {
#pragma unroll
    for (int mi = 0; mi < 2; mi++)
#pragma unroll
        for (int kh = 0; kh < 2; kh++) {
            uint32_t ad = sA + (warp_m0 + mi*16 + (lane & 15)) * RSTRIDE
                             + (kh*16 + (lane >> 4) * 8) * 2;
            ldsm4(a[mi][kh], ad);
        }
}

__device__ __forceinline__ void compute_warp(
    uint32_t sB, const uint32_t a[2][2][4],
    float acc[2][4][4], int warp_n0, int lane)
{
#pragma unroll
    for (int nj2 = 0; nj2 < 2; nj2++) {
#pragma unroll
        for (int kh = 0; kh < 2; kh++) {
            uint32_t r[4];
            uint32_t bd = sB + (warp_n0 + nj2*16 + (lane & 15)) * RSTRIDE
                             + (kh*16 + (lane >> 4) * 8) * 2;
            ldsm4(r, bd);
            mma16816(acc[0][nj2*2 + 0], a[0][kh], r[0], r[2]);
            mma16816(acc[0][nj2*2 + 1], a[0][kh], r[1], r[3]);
            mma16816(acc[1][nj2*2 + 0], a[1][kh], r[0], r[2]);
            mma16816(acc[1][nj2*2 + 1], a[1][kh], r[1], r[3]);
        }
    }
}

__device__ __forceinline__ void load_a4(uint32_t sA, uint32_t a[4][2][4], int warp_m0, int lane) {
#pragma unroll
    for (int mi = 0; mi < 4; mi++)
#pragma unroll
        for (int kh = 0; kh < 2; kh++) {
            uint32_t ad = sA + (warp_m0 + mi*16 + (lane & 15)) * RSTRIDE
                             + (kh*16 + (lane >> 4) * 8) * 2;
            ldsm4(a[mi][kh], ad);
        }
}

__device__ __forceinline__ void compute_warp4(
    uint32_t sB, const uint32_t a[4][2][4],
    float acc[4][4][4], int warp_n0, int lane)
{
#pragma unroll
    for (int nj2 = 0; nj2 < 2; nj2++) {
#pragma unroll
        for (int kh = 0; kh < 2; kh++) {
            uint32_t r[4];
            uint32_t bd = sB + (warp_n0 + nj2*16 + (lane & 15)) * RSTRIDE
                             + (kh*16 + (lane >> 4) * 8) * 2;
            ldsm4(r, bd);
#pragma unroll
            for (int mi = 0; mi < 4; mi++) {
                mma16816(acc[mi][nj2*2 + 0], a[mi][kh], r[0], r[2]);
                mma16816(acc[mi][nj2*2 + 1], a[mi][kh], r[1], r[3]);
            }
        }
    }
}

// ------- launch 2 (PROFILED): GEMM1, CTA 128m x 64n, 4m x 2n warps, 4-stage -------
__global__ __launch_bounds__(256, 2) void k_gemm1(float* __restrict__ out, int out_size) {
    extern __shared__ char smem[];
    // aux loss (router stats finalized by previous launch)
    if (blockIdx.x == 0 && blockIdx.y == 0 && blockIdx.z == 0 && threadIdx.x == 0) {
        float s = 0.f;
        for (int e = 0; e < NE; e++)
            s += ((float)g_dcnt[e] / (float)T_TOK) * (g_psum[e] / (float)T_TOK);
        if (out_size > T_TOK * D_DIM) out[T_TOK * D_DIM] = 0.01f * s * (float)NE;
    }

    const int e = blockIdx.z;
    const int cnt = g_cnt[e];
    const int m0 = blockIdx.x * 128;
    if (m0 >= cnt) return;
    const int base = e * ECAP;
    const int n0g = blockIdx.y * 64;               // 11 tiles cover 704
    const int tid = threadIdx.x, wid = tid >> 5, lane = tid & 31;
    const int warp_m0 = (wid >> 1) * 32, warp_n0 = (wid & 1) * 32;

    uint32_t sb = smem_to_u32(smem);
    const __half* B1 = w1c + (size_t)e * H_DIM * KW1;
    const __half* B3 = w3c + (size_t)e * H_DIM * KW1;
    const long arow = base + m0;

    const int arow_t = tid >> 1, ach = (tid & 1) * 2;
    const __half* gA = xg1 + (arow + arow_t) * (long)KW1 + ach * 8;
    const uint32_t sdA = sb + arow_t * RSTRIDE + ach * 16;

    const int brow = tid >> 2, bch = tid & 3;
    int nr = n0g + brow; if (nr > H_DIM - 1) nr = H_DIM - 1;
    const __half* gB1 = B1 + (long)nr * KW1 + bch * 8;
    const __half* gB3 = B3 + (long)nr * KW1 + bch * 8;
    const uint32_t sdB1 = sb + T128_B + brow * RSTRIDE + bch * 16;
    const uint32_t sdB3 = sdB1 + T64_B;

    auto load_stage = [&](int st, int kc) {
        uint32_t d = st * STAGE1;
        int ko = kc * 32;
        cp16(sdA  + d,      gA  + ko);
        cp16(sdA  + d + 16, gA  + ko + 8);
        cp16(sdB1 + d,      gB1 + ko);
        cp16(sdB3 + d,      gB3 + ko);
    };

    float acc1[2][4][4] = {{{0}}}, acc3[2][4][4] = {{{0}}};

    load_stage(0, 0); CP_COMMIT();
    load_stage(1, 1); CP_COMMIT();
    load_stage(2, 2); CP_COMMIT();

#pragma unroll 4
    for (int kc = 0; kc < NCH1; kc++) {
        CP_WAIT2();
        __syncthreads();
        if (kc + 3 < NCH1) load_stage((kc + 3) & 3, kc + 3);
        CP_COMMIT();
        uint32_t st = sb + (kc & 3) * STAGE1;
        uint32_t a[2][2][4];
        load_a(st, a, warp_m0, lane);
        compute_warp(st + T128_B,         a, acc1, warp_n0, lane); // A*B1
        compute_warp(st + T128_B + T64_B, a, acc3, warp_n0, lane); // A*B3
    }

    // epilogue: swiglu -> single fp16 h
#pragma unroll
    for (int mi = 0; mi < 2; mi++) {
#pragma unroll
        for (int nj = 0; nj < 4; nj++) {
            int n = n0g + warp_n0 + nj * 8 + ((lane & 3) << 1);
            if (n >= HP) continue;
            bool live = (n < H_DIM);
#pragma unroll
            for (int h = 0; h < 2; h++) {
                int rl = warp_m0 + mi * 16 + (lane >> 2) + h * 8;
                int r = m0 + rl;
                if (r >= cnt) continue;
                float v1a = acc1[mi][nj][2*h],   v3a = acc3[mi][nj][2*h];
                float v1b = acc1[mi][nj][2*h+1], v3b = acc3[mi][nj][2*h+1];
                float ha = live ? (v1a / (1.f + __expf(-v1a))) * v3a : 0.f;
                float hb = live ? (v1b / (1.f + __expf(-v1b))) * v3b : 0.f;
                size_t rb = (size_t)(base + r) * KW2;
                *reinterpret_cast<__half2*>(h2_ + rb + n) = __floats2half2_rn(ha, hb);
            }
        }
    }
}

// ------- launch 3: GEMM2 + fused combine, CTA 128m x 128n, warp tile 64x32 -------
__global__ __launch_bounds__(256, 2) void k_gemm2(float* __restrict__ out) {
    extern __shared__ char smem[];
    const int e = blockIdx.z;
    const int cnt = g_cnt[e];
    const int m0 = blockIdx.x * 128;
    if (m0 >= cnt) return;
    const int base = e * ECAP;
    const int n0g = blockIdx.y * 128;
    const int tid = threadIdx.x, wid = tid >> 5, lane = tid & 31;
    const int warp_m0 = (wid >> 2) * 64, warp_n0 = (wid & 3) * 32;

    uint32_t sb = smem_to_u32(smem);
    const __half* B = w2c + (size_t)e * D_DIM * KW2;
    const long arow = base + m0;

    const int arow_t = tid >> 1, ach = (tid & 1) * 2;
    const __half* gA = h2_ + (arow + arow_t) * (long)KW2 + ach * 8;
    const uint32_t sdA = sb + arow_t * RSTRIDE + ach * 16;

    int nr = n0g + arow_t;           // < 1024 always
    const __half* gB = B + (long)nr * KW2 + ach * 8;
    const uint32_t sdB = sb + T128_B + arow_t * RSTRIDE + ach * 16;

    auto load_stage = [&](int st, int kc) {
        uint32_t d = st * STAGE2;
        int ko = kc * 32;
        cp16(sdA + d,      gA + ko);
        cp16(sdA + d + 16, gA + ko + 8);
        cp16(sdB + d,      gB + ko);
        cp16(sdB + d + 16, gB + ko + 8);
    };

    float acc[4][4][4] = {{{0}}};

    load_stage(0, 0); CP_COMMIT();
    load_stage(1, 1); CP_COMMIT();
    load_stage(2, 2); CP_COMMIT();

#pragma unroll 2
    for (int kc = 0; kc < NCH2; kc++) {
        CP_WAIT2();
        __syncthreads();
        if (kc + 3 < NCH2) load_stage((kc + 3) & 3, kc + 3);
        CP_COMMIT();
        uint32_t st = sb + (kc & 3) * STAGE2;
        uint32_t a[4][2][4];
        load_a4(st, a, warp_m0, lane);
        compute_warp4(st + T128_B, a, acc, warp_n0, lane);  // A*B
    }

    // fused combine epilogue: out[tok] += comb * y  (exactly 2 adds per element)
#pragma unroll
    for (int mi = 0; mi < 4; mi++) {
#pragma unroll
        for (int h = 0; h < 2; h++) {
            int rl = warp_m0 + mi * 16 + (lane >> 2) + h * 8;
            int r = m0 + rl;
            if (r >= cnt) continue;
            int tok = g_rows[base + r];
            float cw = g_comb[base + r];
            float* orow = out + (size_t)tok * D_DIM;
#pragma unroll
            for (int nj = 0; nj < 4; nj++) {
                int n = n0g + warp_n0 + nj * 8 + ((lane & 3) << 1);
                atomicAdd(&orow[n],     acc[mi][nj][2*h]     * cw);
                atomicAdd(&orow[n + 1], acc[mi][nj][2*h + 1] * cw);
            }
        }
    }
}

// ======================= launch =======================
extern "C" void kernel_launch(void* const* d_in, const int* in_sizes, int n_in,
                              void* d_out, int out_size) {
    const float* x  = (const float*)d_in[0];
    const float* rw = (const float*)d_in[1];
    const float* w1 = (const float*)d_in[2];
    const float* w2 = (const float*)d_in[3];
    const float* w3 = (const float*)d_in[4];
    float* out = (float*)d_out;

    cudaFuncSetAttribute(k_gemm1, cudaFuncAttributeMaxDynamicSharedMemorySize, 4 * STAGE1);
    cudaFuncSetAttribute(k_gemm2, cudaFuncAttributeMaxDynamicSharedMemorySize, 4 * STAGE2);

    k_init0<<<1, 32>>>();                                                        // #1
    k_main<<<CONV13_BLOCKS + CONV2_BLOCKS + ROUTER_BLOCKS, 256>>>(
        w1, w3, w2, x, rw, out);                                                 // #2
    k_gemm1<<<dim3(64, 11, 8), 256, 4 * STAGE1>>>(out, out_size);                // #3 <- profiled
    k_gemm2<<<dim3(64, 8, 8), 256, 4 * STAGE2>>>(out);                           // #4
}